// round 1
// baseline (speedup 1.0000x reference)
#include <cuda_runtime.h>
#include <cuda_bf16.h>
#include <math.h>

// Problem constants (fixed-shape problem)
#define B_  64
#define S_  512
#define H_  768
#define U_  16
#define C_  5
#define NSEG (B_ * U_)   // 1024

// Scratch (no allocation allowed)
__device__ float g_means[NSEG * H_];   // per-utterance means [1024, 768]
__device__ float g_h[NSEG * H_];       // SELU(means @ W_h + b_h)
__device__ float g_inv[NSEG];          // 1 / max(count, 1)

// ---------------------------------------------------------------------------
// Kernel 1: per-(batch,utterance) inverse counts. grid = B_, block = 256.
// ---------------------------------------------------------------------------
__global__ void counts_kernel(const int* __restrict__ seg) {
    int b = blockIdx.x;
    __shared__ int hist[U_];
    if (threadIdx.x < U_) hist[threadIdx.x] = 0;
    __syncthreads();
    for (int s = threadIdx.x; s < S_; s += blockDim.x) {
        atomicAdd(&hist[seg[b * S_ + s]], 1);
    }
    __syncthreads();
    if (threadIdx.x < U_) {
        float c = (float)hist[threadIdx.x];
        g_inv[b * U_ + threadIdx.x] = 1.0f / fmaxf(c, 1.0f);
    }
}

// ---------------------------------------------------------------------------
// Kernel 2: segment means. segment_ids are sorted per row, so each utterance
// is a contiguous token span -> monotone running-sum, direct stores (no
// atomics), and explicit zero-fill of empty segments.
// grid = (H_/128, B_), block = 128. Each thread owns one hidden column.
// ---------------------------------------------------------------------------
__global__ void seg_mean_kernel(const float* __restrict__ hidden,
                                const int* __restrict__ seg) {
    int b   = blockIdx.y;
    int col = blockIdx.x * 128 + threadIdx.x;

    __shared__ int   sseg[S_];
    __shared__ float sinv[U_];
    for (int i = threadIdx.x; i < S_; i += 128) sseg[i] = seg[b * S_ + i];
    if (threadIdx.x < U_) sinv[threadIdx.x] = g_inv[b * U_ + threadIdx.x];
    __syncthreads();

    const float* hp = hidden + (size_t)b * S_ * H_ + col;
    float* mb = g_means + (size_t)b * U_ * H_ + col;

    int cur = sseg[0];
    // zero leading empty segments
    for (int u = 0; u < cur; ++u) mb[(size_t)u * H_] = 0.0f;

    float acc = 0.0f;
    #pragma unroll 4
    for (int s = 0; s < S_; ++s) {
        float v = hp[(size_t)s * H_];
        int sg = sseg[s];
        if (sg != cur) {
            mb[(size_t)cur * H_] = acc * sinv[cur];
            for (int u = cur + 1; u < sg; ++u) mb[(size_t)u * H_] = 0.0f;
            cur = sg;
            acc = 0.0f;
        }
        acc += v;
    }
    mb[(size_t)cur * H_] = acc * sinv[cur];
    for (int u = cur + 1; u < U_; ++u) mb[(size_t)u * H_] = 0.0f;
}

// ---------------------------------------------------------------------------
// Kernel 3: h = SELU(means @ W_h + b_h).  Classic smem-tiled fp32 GEMM.
// A: [1024,768] (g_means), W: [768,768] row-major, out: g_h [1024,768].
// Tile: BM=32, BN=128, BK=16; block = 256 threads; thread tile 4x4.
// grid = (768/BN, 1024/BM) = (6, 32).
// ---------------------------------------------------------------------------
#define BM 32
#define BN 128
#define BK 16

__global__ __launch_bounds__(256) void gemm1_selu_kernel(
    const float* __restrict__ W, const float* __restrict__ bias) {
    __shared__ float As[BK][BM];       // A transposed tile
    __shared__ float Bs[BK][BN];

    const int tid  = threadIdx.x;      // 0..255
    const int tx   = tid & 31;         // 32 column groups (4 cols each)
    const int ty   = tid >> 5;         // 8 row groups (4 rows each)
    const int row0 = blockIdx.y * BM;
    const int col0 = blockIdx.x * BN;

    float acc[4][4] = {};

    for (int k0 = 0; k0 < H_; k0 += BK) {
        // Load A tile: BM x BK = 512 floats, 2 per thread (float2)
        {
            int idx = tid * 2;
            int r = idx / BK, k = idx % BK;
            float2 v = *(const float2*)(g_means + (size_t)(row0 + r) * H_ + k0 + k);
            As[k][r]     = v.x;
            As[k + 1][r] = v.y;
        }
        // Load B tile: BK x BN = 2048 floats, 2 float4 per thread, coalesced
        #pragma unroll
        for (int i = 0; i < 2; ++i) {
            int lin = (tid + i * 256) * 4;
            int kb = lin / BN, cb = lin % BN;
            *(float4*)&Bs[kb][cb] =
                *(const float4*)(W + (size_t)(k0 + kb) * H_ + col0 + cb);
        }
        __syncthreads();

        #pragma unroll
        for (int kk = 0; kk < BK; ++kk) {
            float a[4], bv[4];
            *(float4*)a  = *(const float4*)&As[kk][ty * 4];
            *(float4*)bv = *(const float4*)&Bs[kk][tx * 4];
            #pragma unroll
            for (int i = 0; i < 4; ++i)
                #pragma unroll
                for (int j = 0; j < 4; ++j)
                    acc[i][j] = fmaf(a[i], bv[j], acc[i][j]);
        }
        __syncthreads();
    }

    // Epilogue: + bias, SELU (matches jax.nn.selu: scale * elu(x, alpha))
    const float kScale = 1.0507009873554805f;
    const float kAlpha = 1.6732632423543772f;
    #pragma unroll
    for (int i = 0; i < 4; ++i) {
        int r = row0 + ty * 4 + i;
        #pragma unroll
        for (int j = 0; j < 4; ++j) {
            int c = col0 + tx * 4 + j;
            float x = acc[i][j] + bias[c];
            float y = (x > 0.0f) ? x : kAlpha * expm1f(x);
            g_h[(size_t)r * H_ + c] = kScale * y;
        }
    }
}

// ---------------------------------------------------------------------------
// Kernel 4: logits = h @ W_o + b_o ; softmax over C_=5.
// One warp per output row. block = 256 (8 rows), grid = 1024/8 = 128.
// ---------------------------------------------------------------------------
__global__ __launch_bounds__(256) void gemm2_softmax_kernel(
    const float* __restrict__ Wo, const float* __restrict__ bo,
    float* __restrict__ out) {
    int warp = threadIdx.x >> 5;
    int lane = threadIdx.x & 31;
    int row  = blockIdx.x * 8 + warp;
    if (row >= NSEG) return;

    const float* hr = g_h + (size_t)row * H_;

    float acc[C_] = {};
    for (int k = lane; k < H_; k += 32) {
        float hv = hr[k];
        #pragma unroll
        for (int c = 0; c < C_; ++c)
            acc[c] = fmaf(hv, Wo[(size_t)k * C_ + c], acc[c]);
    }
    // warp reduce each of the 5 partials
    #pragma unroll
    for (int c = 0; c < C_; ++c) {
        #pragma unroll
        for (int off = 16; off > 0; off >>= 1)
            acc[c] += __shfl_xor_sync(0xFFFFFFFFu, acc[c], off);
    }
    if (lane == 0) {
        float logits[C_];
        float mx = -INFINITY;
        #pragma unroll
        for (int c = 0; c < C_; ++c) {
            logits[c] = acc[c] + bo[c];
            mx = fmaxf(mx, logits[c]);
        }
        float sum = 0.0f;
        #pragma unroll
        for (int c = 0; c < C_; ++c) {
            logits[c] = expf(logits[c] - mx);
            sum += logits[c];
        }
        float inv = 1.0f / sum;
        #pragma unroll
        for (int c = 0; c < C_; ++c)
            out[(size_t)row * C_ + c] = logits[c] * inv;
    }
}

// ---------------------------------------------------------------------------
// Launch
// ---------------------------------------------------------------------------
extern "C" void kernel_launch(void* const* d_in, const int* in_sizes, int n_in,
                              void* d_out, int out_size) {
    const float* hidden = (const float*)d_in[0];
    const int*   seg    = (const int*)d_in[1];
    // n_utter may or may not be materialized as a device input; map robustly.
    int base = (n_in >= 7) ? 3 : 2;
    const float* W_h = (const float*)d_in[base + 0];
    const float* b_h = (const float*)d_in[base + 1];
    const float* W_o = (const float*)d_in[base + 2];
    const float* b_o = (const float*)d_in[base + 3];
    float* out = (float*)d_out;

    counts_kernel<<<B_, 256>>>(seg);

    dim3 g2(H_ / 128, B_);
    seg_mean_kernel<<<g2, 128>>>(hidden, seg);

    dim3 g3(H_ / BN, NSEG / BM);   // (6, 32)
    gemm1_selu_kernel<<<g3, 256>>>(W_h, b_h);

    gemm2_softmax_kernel<<<NSEG / 8, 256>>>(W_o, b_o, out);
}

// round 2
// speedup vs baseline: 2.3630x; 2.3630x over previous
#include <cuda_runtime.h>
#include <cuda_bf16.h>
#include <math.h>

// Problem constants (fixed-shape problem)
#define B_  64
#define S_  512
#define H_  768
#define U_  16
#define C_  5
#define NSEG (B_ * U_)   // 1024

// Scratch (no allocation allowed)
__device__ float g_means[NSEG * H_];   // per-utterance means [1024, 768]
__device__ float g_h[NSEG * H_];       // SELU(means @ W_h + b_h)
__device__ float g_inv[NSEG];          // 1 / max(count, 1)
__device__ int   g_start[NSEG];        // global token index where segment starts
__device__ int   g_count[NSEG];        // tokens in segment

// ---------------------------------------------------------------------------
// Kernel 1: per-(batch,utterance) counts + start offsets (ids sorted per row,
// so each segment is a contiguous span). grid = B_, block = 256.
// ---------------------------------------------------------------------------
__global__ void counts_kernel(const int* __restrict__ seg) {
    int b = blockIdx.x;
    __shared__ int hist[U_];
    if (threadIdx.x < U_) hist[threadIdx.x] = 0;
    __syncthreads();
    for (int s = threadIdx.x; s < S_; s += blockDim.x) {
        atomicAdd(&hist[seg[b * S_ + s]], 1);
    }
    __syncthreads();
    if (threadIdx.x == 0) {
        int run = 0;
        #pragma unroll
        for (int u = 0; u < U_; ++u) {
            int c = hist[u];
            g_start[b * U_ + u] = b * S_ + run;
            g_count[b * U_ + u] = c;
            g_inv[b * U_ + u]   = 1.0f / fmaxf((float)c, 1.0f);
            run += c;
        }
    }
}

// ---------------------------------------------------------------------------
// Kernel 2: segment means. One block per segment; 192 threads x float4 = 768
// cols. Pure load+accumulate loop (no stores/branches inside) -> high MLP,
// bandwidth bound. Empty segments naturally produce zeros.
// grid = NSEG, block = 192.
// ---------------------------------------------------------------------------
__global__ __launch_bounds__(192) void seg_mean_kernel(
    const float* __restrict__ hidden) {
    int sgi   = blockIdx.x;
    int start = g_start[sgi];
    int cnt   = g_count[sgi];
    float inv = g_inv[sgi];

    const float4* __restrict__ hp =
        (const float4*)hidden + (size_t)start * (H_ / 4) + threadIdx.x;

    float4 a0 = {0,0,0,0}, a1 = {0,0,0,0}, a2 = {0,0,0,0}, a3 = {0,0,0,0};
    int r = 0;
    for (; r + 4 <= cnt; r += 4) {
        float4 v0 = hp[(size_t)(r + 0) * (H_ / 4)];
        float4 v1 = hp[(size_t)(r + 1) * (H_ / 4)];
        float4 v2 = hp[(size_t)(r + 2) * (H_ / 4)];
        float4 v3 = hp[(size_t)(r + 3) * (H_ / 4)];
        a0.x += v0.x; a0.y += v0.y; a0.z += v0.z; a0.w += v0.w;
        a1.x += v1.x; a1.y += v1.y; a1.z += v1.z; a1.w += v1.w;
        a2.x += v2.x; a2.y += v2.y; a2.z += v2.z; a2.w += v2.w;
        a3.x += v3.x; a3.y += v3.y; a3.z += v3.z; a3.w += v3.w;
    }
    for (; r < cnt; ++r) {
        float4 v = hp[(size_t)r * (H_ / 4)];
        a0.x += v.x; a0.y += v.y; a0.z += v.z; a0.w += v.w;
    }
    float4 acc;
    acc.x = (a0.x + a1.x) + (a2.x + a3.x);
    acc.y = (a0.y + a1.y) + (a2.y + a3.y);
    acc.z = (a0.z + a1.z) + (a2.z + a3.z);
    acc.w = (a0.w + a1.w) + (a2.w + a3.w);
    acc.x *= inv; acc.y *= inv; acc.z *= inv; acc.w *= inv;

    ((float4*)g_means)[(size_t)sgi * (H_ / 4) + threadIdx.x] = acc;
}

// ---------------------------------------------------------------------------
// Kernel 3: h = SELU(means @ W_h + b_h).  Classic smem-tiled fp32 GEMM.
// Tile: BM=32, BN=128, BK=16; block = 256 threads; thread tile 4x4.
// grid = (768/BN, 1024/BM) = (6, 32).
// ---------------------------------------------------------------------------
#define BM 32
#define BN 128
#define BK 16

__global__ __launch_bounds__(256) void gemm1_selu_kernel(
    const float* __restrict__ W, const float* __restrict__ bias) {
    __shared__ float As[BK][BM];       // A transposed tile
    __shared__ float Bs[BK][BN];

    const int tid  = threadIdx.x;      // 0..255
    const int tx   = tid & 31;         // 32 column groups (4 cols each)
    const int ty   = tid >> 5;         // 8 row groups (4 rows each)
    const int row0 = blockIdx.y * BM;
    const int col0 = blockIdx.x * BN;

    float acc[4][4] = {};

    for (int k0 = 0; k0 < H_; k0 += BK) {
        // Load A tile: BM x BK = 512 floats, 2 per thread (float2)
        {
            int idx = tid * 2;
            int r = idx / BK, k = idx % BK;
            float2 v = *(const float2*)(g_means + (size_t)(row0 + r) * H_ + k0 + k);
            As[k][r]     = v.x;
            As[k + 1][r] = v.y;
        }
        // Load B tile: BK x BN = 2048 floats, 2 float4 per thread, coalesced
        #pragma unroll
        for (int i = 0; i < 2; ++i) {
            int lin = (tid + i * 256) * 4;
            int kb = lin / BN, cb = lin % BN;
            *(float4*)&Bs[kb][cb] =
                *(const float4*)(W + (size_t)(k0 + kb) * H_ + col0 + cb);
        }
        __syncthreads();

        #pragma unroll
        for (int kk = 0; kk < BK; ++kk) {
            float a[4], bv[4];
            *(float4*)a  = *(const float4*)&As[kk][ty * 4];
            *(float4*)bv = *(const float4*)&Bs[kk][tx * 4];
            #pragma unroll
            for (int i = 0; i < 4; ++i)
                #pragma unroll
                for (int j = 0; j < 4; ++j)
                    acc[i][j] = fmaf(a[i], bv[j], acc[i][j]);
        }
        __syncthreads();
    }

    // Epilogue: + bias, SELU (matches jax.nn.selu: scale * elu(x, alpha))
    const float kScale = 1.0507009873554805f;
    const float kAlpha = 1.6732632423543772f;
    #pragma unroll
    for (int i = 0; i < 4; ++i) {
        int r = row0 + ty * 4 + i;
        #pragma unroll
        for (int j = 0; j < 4; ++j) {
            int c = col0 + tx * 4 + j;
            float x = acc[i][j] + bias[c];
            float y = (x > 0.0f) ? x : kAlpha * expm1f(x);
            g_h[(size_t)r * H_ + c] = kScale * y;
        }
    }
}

// ---------------------------------------------------------------------------
// Kernel 4: logits = h @ W_o + b_o ; softmax over C_=5.
// Wo staged in smem (stride-5 word access is conflict-free mod 32 banks).
// One warp per output row. block = 256 (8 rows), grid = 1024/8 = 128.
// ---------------------------------------------------------------------------
__global__ __launch_bounds__(256) void gemm2_softmax_kernel(
    const float* __restrict__ Wo, const float* __restrict__ bo,
    float* __restrict__ out) {
    __shared__ float sW[H_ * C_];       // 15360 B
    for (int i = threadIdx.x; i < H_ * C_; i += 256) sW[i] = Wo[i];
    __syncthreads();

    int warp = threadIdx.x >> 5;
    int lane = threadIdx.x & 31;
    int row  = blockIdx.x * 8 + warp;

    const float* __restrict__ hr = g_h + (size_t)row * H_;

    float acc[C_] = {};
    #pragma unroll 4
    for (int it = 0; it < H_ / 32; ++it) {
        int k = it * 32 + lane;
        float hv = hr[k];
        #pragma unroll
        for (int c = 0; c < C_; ++c)
            acc[c] = fmaf(hv, sW[k * C_ + c], acc[c]);
    }
    // warp reduce each of the 5 partials
    #pragma unroll
    for (int c = 0; c < C_; ++c) {
        #pragma unroll
        for (int off = 16; off > 0; off >>= 1)
            acc[c] += __shfl_xor_sync(0xFFFFFFFFu, acc[c], off);
    }
    if (lane == 0) {
        float logits[C_];
        float mx = -INFINITY;
        #pragma unroll
        for (int c = 0; c < C_; ++c) {
            logits[c] = acc[c] + bo[c];
            mx = fmaxf(mx, logits[c]);
        }
        float sum = 0.0f;
        #pragma unroll
        for (int c = 0; c < C_; ++c) {
            logits[c] = expf(logits[c] - mx);
            sum += logits[c];
        }
        float inv = 1.0f / sum;
        #pragma unroll
        for (int c = 0; c < C_; ++c)
            out[(size_t)row * C_ + c] = logits[c] * inv;
    }
}

// ---------------------------------------------------------------------------
// Launch
// ---------------------------------------------------------------------------
extern "C" void kernel_launch(void* const* d_in, const int* in_sizes, int n_in,
                              void* d_out, int out_size) {
    const float* hidden = (const float*)d_in[0];
    const int*   seg    = (const int*)d_in[1];
    // n_utter may or may not be materialized as a device input; map robustly.
    int base = (n_in >= 7) ? 3 : 2;
    const float* W_h = (const float*)d_in[base + 0];
    const float* b_h = (const float*)d_in[base + 1];
    const float* W_o = (const float*)d_in[base + 2];
    const float* b_o = (const float*)d_in[base + 3];
    float* out = (float*)d_out;

    counts_kernel<<<B_, 256>>>(seg);

    seg_mean_kernel<<<NSEG, 192>>>(hidden);

    dim3 g3(H_ / BN, NSEG / BM);   // (6, 32)
    gemm1_selu_kernel<<<g3, 256>>>(W_h, b_h);

    gemm2_softmax_kernel<<<NSEG / 8, 256>>>(W_o, b_o, out);
}

// round 4
// speedup vs baseline: 3.5716x; 1.5114x over previous
#include <cuda_runtime.h>
#include <cuda_bf16.h>
#include <math.h>
#include <stdint.h>

// Problem constants (fixed-shape problem)
#define B_  64
#define S_  512
#define H_  768
#define U_  16
#define C_  5
#define NSEG (B_ * U_)     // 1024
#define NTILE_N 12         // 768 / 64 (CTA N tiles)
#define NTILE_M 8          // 1024 / 128
#define NTILE_P (NTILE_N * 2)   // 24 partial-logit slots (per 32-col warp slice)

// ---------------------------------------------------------------------------
// Scratch (no allocation allowed)
// ---------------------------------------------------------------------------
__device__ float g_inv[NSEG];
__device__ int   g_start[NSEG];
__device__ int   g_count[NSEG];
__device__ __align__(16) __nv_bfloat16 g_mean_hi[NSEG * H_];
__device__ __align__(16) __nv_bfloat16 g_mean_lo[NSEG * H_];
__device__ __align__(16) __nv_bfloat16 g_wt_hi[H_ * H_];   // W_h^T: [n][k]
__device__ __align__(16) __nv_bfloat16 g_wt_lo[H_ * H_];
__device__ float g_partial[NTILE_P * NSEG * C_];

// ---------------------------------------------------------------------------
// mma.sync m16n8k16 bf16 (baseline PTX — works on compute_103 target)
// ---------------------------------------------------------------------------
__device__ __forceinline__ void mma_bf16(float* c, const uint32_t* a,
                                         const uint32_t* b) {
    asm volatile(
        "mma.sync.aligned.m16n8k16.row.col.f32.bf16.bf16.f32 "
        "{%0,%1,%2,%3}, {%4,%5,%6,%7}, {%8,%9}, {%0,%1,%2,%3};\n"
        : "+f"(c[0]), "+f"(c[1]), "+f"(c[2]), "+f"(c[3])
        : "r"(a[0]), "r"(a[1]), "r"(a[2]), "r"(a[3]), "r"(b[0]), "r"(b[1]));
}

// ---------------------------------------------------------------------------
// Kernel 1: counts + start offsets (segments contiguous since ids sorted)
// ---------------------------------------------------------------------------
__global__ void counts_kernel(const int* __restrict__ seg) {
    int b = blockIdx.x;
    __shared__ int hist[U_];
    if (threadIdx.x < U_) hist[threadIdx.x] = 0;
    __syncthreads();
    for (int s = threadIdx.x; s < S_; s += blockDim.x)
        atomicAdd(&hist[seg[b * S_ + s]], 1);
    __syncthreads();
    if (threadIdx.x == 0) {
        int run = 0;
        #pragma unroll
        for (int u = 0; u < U_; ++u) {
            int c = hist[u];
            g_start[b * U_ + u] = b * S_ + run;
            g_count[b * U_ + u] = c;
            g_inv[b * U_ + u]   = 1.0f / fmaxf((float)c, 1.0f);
            run += c;
        }
    }
}

// ---------------------------------------------------------------------------
// Kernel 2: W_h transpose + bf16 hi/lo split.  grid (24,24), block (32,8).
// ---------------------------------------------------------------------------
__global__ void wprep_kernel(const float* __restrict__ W) {
    __shared__ float t[32][33];
    int n0 = blockIdx.x * 32, k0 = blockIdx.y * 32;
    #pragma unroll
    for (int r = 0; r < 32; r += 8)
        t[threadIdx.y + r][threadIdx.x] =
            W[(size_t)(k0 + threadIdx.y + r) * H_ + n0 + threadIdx.x];
    __syncthreads();
    int k = k0 + threadIdx.x;
    #pragma unroll
    for (int r = 0; r < 32; r += 8) {
        int n = n0 + threadIdx.y + r;
        float v = t[threadIdx.x][threadIdx.y + r];
        __nv_bfloat16 hi = __float2bfloat16(v);
        __nv_bfloat16 lo = __float2bfloat16(v - __bfloat162float(hi));
        g_wt_hi[(size_t)n * H_ + k] = hi;
        g_wt_lo[(size_t)n * H_ + k] = lo;
    }
}

// ---------------------------------------------------------------------------
// Kernel 3: segment means + bf16 hi/lo split. grid=NSEG, block=192.
// ---------------------------------------------------------------------------
__global__ __launch_bounds__(192) void seg_mean_kernel(
    const float* __restrict__ hidden) {
    int sgi   = blockIdx.x;
    int start = g_start[sgi];
    int cnt   = g_count[sgi];
    float inv = g_inv[sgi];

    const float4* __restrict__ hp =
        (const float4*)hidden + (size_t)start * (H_ / 4) + threadIdx.x;

    float4 a0 = {0,0,0,0}, a1 = {0,0,0,0}, a2 = {0,0,0,0}, a3 = {0,0,0,0};
    int r = 0;
    for (; r + 4 <= cnt; r += 4) {
        float4 v0 = hp[(size_t)(r + 0) * (H_ / 4)];
        float4 v1 = hp[(size_t)(r + 1) * (H_ / 4)];
        float4 v2 = hp[(size_t)(r + 2) * (H_ / 4)];
        float4 v3 = hp[(size_t)(r + 3) * (H_ / 4)];
        a0.x += v0.x; a0.y += v0.y; a0.z += v0.z; a0.w += v0.w;
        a1.x += v1.x; a1.y += v1.y; a1.z += v1.z; a1.w += v1.w;
        a2.x += v2.x; a2.y += v2.y; a2.z += v2.z; a2.w += v2.w;
        a3.x += v3.x; a3.y += v3.y; a3.z += v3.z; a3.w += v3.w;
    }
    for (; r < cnt; ++r) {
        float4 v = hp[(size_t)r * (H_ / 4)];
        a0.x += v.x; a0.y += v.y; a0.z += v.z; a0.w += v.w;
    }
    float m[4];
    m[0] = ((a0.x + a1.x) + (a2.x + a3.x)) * inv;
    m[1] = ((a0.y + a1.y) + (a2.y + a3.y)) * inv;
    m[2] = ((a0.z + a1.z) + (a2.z + a3.z)) * inv;
    m[3] = ((a0.w + a1.w) + (a2.w + a3.w)) * inv;

    __nv_bfloat16 hi[4], lo[4];
    #pragma unroll
    for (int i = 0; i < 4; ++i) {
        hi[i] = __float2bfloat16(m[i]);
        lo[i] = __float2bfloat16(m[i] - __bfloat162float(hi[i]));
    }
    __nv_bfloat162 ph0 = {hi[0], hi[1]}, ph1 = {hi[2], hi[3]};
    __nv_bfloat162 pl0 = {lo[0], lo[1]}, pl1 = {lo[2], lo[3]};
    uint2 uh, ul;
    uh.x = *(uint32_t*)&ph0; uh.y = *(uint32_t*)&ph1;
    ul.x = *(uint32_t*)&pl0; ul.y = *(uint32_t*)&pl1;
    ((uint2*)g_mean_hi)[(size_t)sgi * (H_ / 4) + threadIdx.x] = uh;
    ((uint2*)g_mean_lo)[(size_t)sgi * (H_ / 4) + threadIdx.x] = ul;
}

// ---------------------------------------------------------------------------
// Kernel 4: bf16x3 warp-MMA GEMM (means @ W_h) + bias + SELU + fused partial
// logits vs W_o slice.  grid = (12, 8), block = 256 (8 warps: 4 M x 2 N).
// CTA tile 128(M) x 64(N); warp tile 32x32; K chunks of 32.
// ---------------------------------------------------------------------------
#define KC 32
#define KPAD 40                 // padded row, bf16 (80 B = 5 x 16B)
#define NCHUNK (H_ / KC)        // 24

__global__ __launch_bounds__(256) void gemm_fused_kernel(
    const float* __restrict__ bias, const float* __restrict__ Wo) {
    __shared__ __align__(16) __nv_bfloat16 As_hi[128][KPAD];
    __shared__ __align__(16) __nv_bfloat16 As_lo[128][KPAD];
    __shared__ __align__(16) __nv_bfloat16 Bs_hi[64][KPAD];
    __shared__ __align__(16) __nv_bfloat16 Bs_lo[64][KPAD];
    __shared__ float sWo[64 * C_];
    __shared__ float sBias[64];

    const int tid  = threadIdx.x;
    const int wid  = tid >> 5;
    const int lane = tid & 31;
    const int warp_m = wid & 3;     // 0..3
    const int warp_n = wid >> 2;    // 0..1
    const int n0 = blockIdx.x * 64;
    const int m0 = blockIdx.y * 128;

    for (int i = tid; i < 64 * C_; i += 256) sWo[i] = Wo[(size_t)n0 * C_ + i];
    if (tid < 64) sBias[tid] = bias[n0 + tid];

    const __nv_bfloat16* __restrict__ Ahi = g_mean_hi + (size_t)m0 * H_;
    const __nv_bfloat16* __restrict__ Alo = g_mean_lo + (size_t)m0 * H_;
    const __nv_bfloat16* __restrict__ Bhi = g_wt_hi + (size_t)n0 * H_;
    const __nv_bfloat16* __restrict__ Blo = g_wt_lo + (size_t)n0 * H_;

    // prefetch registers
    uint4 pa_hi[2], pa_lo[2], pb_hi, pb_lo;
    const int a_row0 = tid >> 2,        a_u0 = (tid & 3);        // i=0
    const int a_row1 = (tid + 256) >> 2, a_u1 = ((tid + 256) & 3);
    const int b_row  = tid >> 2,        b_u  = (tid & 3);
    {
        const int k0 = 0;
        pa_hi[0] = *(const uint4*)(Ahi + (size_t)a_row0 * H_ + k0 + a_u0 * 8);
        pa_lo[0] = *(const uint4*)(Alo + (size_t)a_row0 * H_ + k0 + a_u0 * 8);
        pa_hi[1] = *(const uint4*)(Ahi + (size_t)a_row1 * H_ + k0 + a_u1 * 8);
        pa_lo[1] = *(const uint4*)(Alo + (size_t)a_row1 * H_ + k0 + a_u1 * 8);
        pb_hi    = *(const uint4*)(Bhi + (size_t)b_row * H_ + k0 + b_u * 8);
        pb_lo    = *(const uint4*)(Blo + (size_t)b_row * H_ + k0 + b_u * 8);
    }

    float acc[2][4][4] = {};   // [mt][nt][elem]

    const uint32_t* Aw_hi = (const uint32_t*)As_hi;   // row stride 20 words
    const uint32_t* Aw_lo = (const uint32_t*)As_lo;
    const uint32_t* Bw_hi = (const uint32_t*)Bs_hi;
    const uint32_t* Bw_lo = (const uint32_t*)Bs_lo;

    for (int ck = 0; ck < NCHUNK; ++ck) {
        __syncthreads();   // previous chunk's mma reads done (and sWo ready)

        *(uint4*)&As_hi[a_row0][a_u0 * 8] = pa_hi[0];
        *(uint4*)&As_lo[a_row0][a_u0 * 8] = pa_lo[0];
        *(uint4*)&As_hi[a_row1][a_u1 * 8] = pa_hi[1];
        *(uint4*)&As_lo[a_row1][a_u1 * 8] = pa_lo[1];
        *(uint4*)&Bs_hi[b_row][b_u * 8] = pb_hi;
        *(uint4*)&Bs_lo[b_row][b_u * 8] = pb_lo;

        if (ck + 1 < NCHUNK) {
            const int k0 = (ck + 1) * KC;
            pa_hi[0] = *(const uint4*)(Ahi + (size_t)a_row0 * H_ + k0 + a_u0 * 8);
            pa_lo[0] = *(const uint4*)(Alo + (size_t)a_row0 * H_ + k0 + a_u0 * 8);
            pa_hi[1] = *(const uint4*)(Ahi + (size_t)a_row1 * H_ + k0 + a_u1 * 8);
            pa_lo[1] = *(const uint4*)(Alo + (size_t)a_row1 * H_ + k0 + a_u1 * 8);
            pb_hi    = *(const uint4*)(Bhi + (size_t)b_row * H_ + k0 + b_u * 8);
            pb_lo    = *(const uint4*)(Blo + (size_t)b_row * H_ + k0 + b_u * 8);
        }
        __syncthreads();

        #pragma unroll
        for (int ks = 0; ks < KC / 16; ++ks) {
            const int kw = ks * 8;   // word offset of this k16 step
            // B fragments (col-major k16 x n8): b0 at (k=2q, n), b1 at k+8
            uint32_t bh[4][2], bl[4][2];
            #pragma unroll
            for (int nt = 0; nt < 4; ++nt) {
                int n = warp_n * 32 + nt * 8 + (lane >> 2);
                int c = kw + (lane & 3);
                bh[nt][0] = Bw_hi[n * (KPAD / 2) + c];
                bh[nt][1] = Bw_hi[n * (KPAD / 2) + c + 4];
                bl[nt][0] = Bw_lo[n * (KPAD / 2) + c];
                bl[nt][1] = Bw_lo[n * (KPAD / 2) + c + 4];
            }
            #pragma unroll
            for (int mt = 0; mt < 2; ++mt) {
                int r = warp_m * 32 + mt * 16 + (lane >> 2);
                int c = kw + (lane & 3);
                uint32_t ah[4], al[4];
                ah[0] = Aw_hi[r * (KPAD / 2) + c];
                ah[1] = Aw_hi[(r + 8) * (KPAD / 2) + c];
                ah[2] = Aw_hi[r * (KPAD / 2) + c + 4];
                ah[3] = Aw_hi[(r + 8) * (KPAD / 2) + c + 4];
                al[0] = Aw_lo[r * (KPAD / 2) + c];
                al[1] = Aw_lo[(r + 8) * (KPAD / 2) + c];
                al[2] = Aw_lo[r * (KPAD / 2) + c + 4];
                al[3] = Aw_lo[(r + 8) * (KPAD / 2) + c + 4];
                #pragma unroll
                for (int nt = 0; nt < 4; ++nt) {
                    mma_bf16(acc[mt][nt], ah, bh[nt]);
                    mma_bf16(acc[mt][nt], ah, bl[nt]);
                    mma_bf16(acc[mt][nt], al, bh[nt]);
                }
            }
        }
    }

    // ---- epilogue: bias + SELU + partial logits ----
    const float kScale = 1.0507009873554805f;
    const float kAlpha = 1.6732632423543772f;
    float pl[4][C_] = {};   // rows: mt*2 + (upper8)
    #pragma unroll
    for (int mt = 0; mt < 2; ++mt) {
        #pragma unroll
        for (int nt = 0; nt < 4; ++nt) {
            #pragma unroll
            for (int e = 0; e < 4; ++e) {
                int col = warp_n * 32 + nt * 8 + (lane & 3) * 2 + (e & 1);
                float x = acc[mt][nt][e] + sBias[col];
                float y = (x > 0.0f) ? x : kAlpha * expm1f(x);
                float h = kScale * y;
                int ridx = mt * 2 + (e >> 1);
                #pragma unroll
                for (int c = 0; c < C_; ++c)
                    pl[ridx][c] = fmaf(h, sWo[col * C_ + c], pl[ridx][c]);
            }
        }
    }
    // quad reduce (lanes sharing lane>>2 hold same rows, different cols)
    #pragma unroll
    for (int ridx = 0; ridx < 4; ++ridx)
        #pragma unroll
        for (int c = 0; c < C_; ++c) {
            pl[ridx][c] += __shfl_xor_sync(0xFFFFFFFFu, pl[ridx][c], 1);
            pl[ridx][c] += __shfl_xor_sync(0xFFFFFFFFu, pl[ridx][c], 2);
        }
    if ((lane & 3) == 0) {
        int slot = blockIdx.x * 2 + warp_n;
        #pragma unroll
        for (int ridx = 0; ridx < 4; ++ridx) {
            int row = m0 + warp_m * 32 + (ridx >> 1) * 16 + (lane >> 2) +
                      (ridx & 1) * 8;
            float* dst = g_partial + ((size_t)slot * NSEG + row) * C_;
            #pragma unroll
            for (int c = 0; c < C_; ++c) dst[c] = pl[ridx][c];
        }
    }
}

// ---------------------------------------------------------------------------
// Kernel 5: reduce 24 partial slots + b_o, softmax.  grid=4, block=256.
// ---------------------------------------------------------------------------
__global__ __launch_bounds__(256) void softmax_kernel(
    const float* __restrict__ bo, float* __restrict__ out) {
    int row = blockIdx.x * 256 + threadIdx.x;
    float l[C_];
    #pragma unroll
    for (int c = 0; c < C_; ++c) l[c] = bo[c];
    #pragma unroll
    for (int t = 0; t < NTILE_P; ++t) {
        const float* p = g_partial + ((size_t)t * NSEG + row) * C_;
        #pragma unroll
        for (int c = 0; c < C_; ++c) l[c] += p[c];
    }
    float mx = -INFINITY;
    #pragma unroll
    for (int c = 0; c < C_; ++c) mx = fmaxf(mx, l[c]);
    float sum = 0.0f;
    #pragma unroll
    for (int c = 0; c < C_; ++c) { l[c] = expf(l[c] - mx); sum += l[c]; }
    float inv = 1.0f / sum;
    #pragma unroll
    for (int c = 0; c < C_; ++c) out[(size_t)row * C_ + c] = l[c] * inv;
}

// ---------------------------------------------------------------------------
// Launch
// ---------------------------------------------------------------------------
extern "C" void kernel_launch(void* const* d_in, const int* in_sizes, int n_in,
                              void* d_out, int out_size) {
    const float* hidden = (const float*)d_in[0];
    const int*   seg    = (const int*)d_in[1];
    int base = (n_in >= 7) ? 3 : 2;
    const float* W_h = (const float*)d_in[base + 0];
    const float* b_h = (const float*)d_in[base + 1];
    const float* W_o = (const float*)d_in[base + 2];
    const float* b_o = (const float*)d_in[base + 3];
    float* out = (float*)d_out;

    counts_kernel<<<B_, 256>>>(seg);

    dim3 gw(H_ / 32, H_ / 32);
    wprep_kernel<<<gw, dim3(32, 8)>>>(W_h);

    seg_mean_kernel<<<NSEG, 192>>>(hidden);

    dim3 gg(NTILE_N, NTILE_M);   // (12, 8) = 96 CTAs
    gemm_fused_kernel<<<gg, 256>>>(b_h, W_o);

    softmax_kernel<<<NSEG / 256, 256>>>(b_o, out);
}

// round 5
// speedup vs baseline: 4.2475x; 1.1892x over previous
#include <cuda_runtime.h>
#include <cuda_bf16.h>
#include <math.h>
#include <stdint.h>

// Problem constants (fixed-shape problem)
#define B_  64
#define S_  512
#define H_  768
#define U_  16
#define C_  5
#define NSEG (B_ * U_)       // 1024
#define NTILE_N 12           // 768 / 64
#define NTILE_M 16           // 1024 / 64
#define NTILE_P (NTILE_N * 2)  // 24 partial slots (32-col warp slices)
#define NWPREP  576          // 24 x 24 transpose blocks

// ---------------------------------------------------------------------------
// Scratch (no allocation allowed)
// ---------------------------------------------------------------------------
__device__ __align__(16) __nv_bfloat16 g_mean_hi[NSEG * H_];
__device__ __align__(16) __nv_bfloat16 g_mean_lo[NSEG * H_];
__device__ __align__(16) __nv_bfloat16 g_wt_hi[H_ * H_];   // W_h^T: [n][k]
__device__ __align__(16) __nv_bfloat16 g_wt_lo[H_ * H_];
__device__ float g_partial[NTILE_P * NSEG * C_];

// ---------------------------------------------------------------------------
// PTX helpers (baseline PTX only — compiles for compute_103)
// ---------------------------------------------------------------------------
__device__ __forceinline__ void mma_bf16(float* c, const uint32_t* a,
                                         const uint32_t* b) {
    asm volatile(
        "mma.sync.aligned.m16n8k16.row.col.f32.bf16.bf16.f32 "
        "{%0,%1,%2,%3}, {%4,%5,%6,%7}, {%8,%9}, {%0,%1,%2,%3};\n"
        : "+f"(c[0]), "+f"(c[1]), "+f"(c[2]), "+f"(c[3])
        : "r"(a[0]), "r"(a[1]), "r"(a[2]), "r"(a[3]), "r"(b[0]), "r"(b[1]));
}
__device__ __forceinline__ void ldsm_x4(uint32_t* r, uint32_t addr) {
    asm volatile(
        "ldmatrix.sync.aligned.m8n8.x4.shared.b16 {%0,%1,%2,%3}, [%4];"
        : "=r"(r[0]), "=r"(r[1]), "=r"(r[2]), "=r"(r[3]) : "r"(addr));
}
#define CP16(dst, src) \
    asm volatile("cp.async.cg.shared.global [%0], [%1], 16;" \
                 :: "r"(dst), "l"(src))
__device__ __forceinline__ uint32_t s2u(const void* p) {
    return (uint32_t)__cvta_generic_to_shared(p);
}

// ---------------------------------------------------------------------------
// Kernel 1 (merged prep):
//   blocks [0, NSEG): per-segment count + mean + bf16 hi/lo split
//   blocks [NSEG, NSEG+NWPREP): W_h transpose + bf16 hi/lo split
// block = 256.
// ---------------------------------------------------------------------------
__global__ __launch_bounds__(256) void prep_kernel(
    const float* __restrict__ hidden, const int* __restrict__ seg,
    const float* __restrict__ W) {
    const int bid = blockIdx.x;
    const int tid = threadIdx.x;

    if (bid < NSEG) {
        // ---- segment mean ----
        __shared__ int s_lt, s_eq;
        const int b = bid >> 4, u = bid & 15;
        if (tid == 0) { s_lt = 0; s_eq = 0; }
        __syncthreads();
        int2 v = ((const int2*)(seg + (size_t)b * S_))[tid];
        int lt = (v.x < u) + (v.y < u);
        int eq = (v.x == u) + (v.y == u);
        #pragma unroll
        for (int off = 16; off > 0; off >>= 1) {
            lt += __shfl_xor_sync(0xFFFFFFFFu, lt, off);
            eq += __shfl_xor_sync(0xFFFFFFFFu, eq, off);
        }
        if ((tid & 31) == 0) { atomicAdd(&s_lt, lt); atomicAdd(&s_eq, eq); }
        __syncthreads();
        const int start = b * S_ + s_lt;
        const int cnt   = s_eq;
        const float inv = 1.0f / fmaxf((float)cnt, 1.0f);

        if (tid < 192) {
            const float4* __restrict__ hp =
                (const float4*)hidden + (size_t)start * (H_ / 4) + tid;
            float4 a0 = {0,0,0,0}, a1 = {0,0,0,0}, a2 = {0,0,0,0},
                   a3 = {0,0,0,0};
            int r = 0;
            for (; r + 4 <= cnt; r += 4) {
                float4 v0 = hp[(size_t)(r + 0) * (H_ / 4)];
                float4 v1 = hp[(size_t)(r + 1) * (H_ / 4)];
                float4 v2 = hp[(size_t)(r + 2) * (H_ / 4)];
                float4 v3 = hp[(size_t)(r + 3) * (H_ / 4)];
                a0.x += v0.x; a0.y += v0.y; a0.z += v0.z; a0.w += v0.w;
                a1.x += v1.x; a1.y += v1.y; a1.z += v1.z; a1.w += v1.w;
                a2.x += v2.x; a2.y += v2.y; a2.z += v2.z; a2.w += v2.w;
                a3.x += v3.x; a3.y += v3.y; a3.z += v3.z; a3.w += v3.w;
            }
            for (; r < cnt; ++r) {
                float4 vv = hp[(size_t)r * (H_ / 4)];
                a0.x += vv.x; a0.y += vv.y; a0.z += vv.z; a0.w += vv.w;
            }
            float m[4];
            m[0] = ((a0.x + a1.x) + (a2.x + a3.x)) * inv;
            m[1] = ((a0.y + a1.y) + (a2.y + a3.y)) * inv;
            m[2] = ((a0.z + a1.z) + (a2.z + a3.z)) * inv;
            m[3] = ((a0.w + a1.w) + (a2.w + a3.w)) * inv;

            __nv_bfloat16 hi[4], lo[4];
            #pragma unroll
            for (int i = 0; i < 4; ++i) {
                hi[i] = __float2bfloat16(m[i]);
                lo[i] = __float2bfloat16(m[i] - __bfloat162float(hi[i]));
            }
            __nv_bfloat162 ph0 = {hi[0], hi[1]}, ph1 = {hi[2], hi[3]};
            __nv_bfloat162 pl0 = {lo[0], lo[1]}, pl1 = {lo[2], lo[3]};
            uint2 uh, ul;
            uh.x = *(uint32_t*)&ph0; uh.y = *(uint32_t*)&ph1;
            ul.x = *(uint32_t*)&pl0; ul.y = *(uint32_t*)&pl1;
            ((uint2*)g_mean_hi)[(size_t)bid * (H_ / 4) + tid] = uh;
            ((uint2*)g_mean_lo)[(size_t)bid * (H_ / 4) + tid] = ul;
        }
    } else {
        // ---- W_h transpose + split ----
        __shared__ float t[32][33];
        const int w  = bid - NSEG;
        const int n0 = (w % 24) * 32, k0 = (w / 24) * 32;
        const int tx = tid & 31, ty = tid >> 5;   // 32 x 8
        #pragma unroll
        for (int r = 0; r < 32; r += 8)
            t[ty + r][tx] = W[(size_t)(k0 + ty + r) * H_ + n0 + tx];
        __syncthreads();
        const int k = k0 + tx;
        #pragma unroll
        for (int r = 0; r < 32; r += 8) {
            const int n = n0 + ty + r;
            float v = t[tx][ty + r];
            __nv_bfloat16 hi = __float2bfloat16(v);
            __nv_bfloat16 lo = __float2bfloat16(v - __bfloat162float(hi));
            g_wt_hi[(size_t)n * H_ + k] = hi;
            g_wt_lo[(size_t)n * H_ + k] = lo;
        }
    }
}

// ---------------------------------------------------------------------------
// Kernel 2: bf16x3 warp-MMA GEMM + bias + SELU + fused partial logits.
// CTA tile 64x64, block = 128 (4 warps: 2M x 2N, warp tile 32x32).
// K chunks of 32, 2-stage cp.async pipeline, ldmatrix fragment loads.
// grid = (12, 16) = 192 CTAs.
// ---------------------------------------------------------------------------
#define TM 64
#define TN 64
#define KC 32
#define KPAD 40
#define NCHUNK (H_ / KC)   // 24

__global__ __launch_bounds__(128) void gemm_fused_kernel(
    const float* __restrict__ bias, const float* __restrict__ Wo) {
    __shared__ __align__(16) __nv_bfloat16 sA_hi[2][TM][KPAD];
    __shared__ __align__(16) __nv_bfloat16 sA_lo[2][TM][KPAD];
    __shared__ __align__(16) __nv_bfloat16 sB_hi[2][TN][KPAD];
    __shared__ __align__(16) __nv_bfloat16 sB_lo[2][TN][KPAD];
    __shared__ float sWo[TN * C_];
    __shared__ float sBias[TN];

    const int tid  = threadIdx.x;
    const int wid  = tid >> 5;
    const int lane = tid & 31;
    const int warp_m = wid & 1;
    const int warp_n = wid >> 1;
    const int n0 = blockIdx.x * TN;
    const int m0 = blockIdx.y * TM;

    for (int i = tid; i < TN * C_; i += 128) sWo[i] = Wo[(size_t)n0 * C_ + i];
    if (tid < TN) sBias[tid] = bias[n0 + tid];

    const __nv_bfloat16* __restrict__ Ahi = g_mean_hi + (size_t)m0 * H_;
    const __nv_bfloat16* __restrict__ Alo = g_mean_lo + (size_t)m0 * H_;
    const __nv_bfloat16* __restrict__ Bhi = g_wt_hi + (size_t)n0 * H_;
    const __nv_bfloat16* __restrict__ Blo = g_wt_lo + (size_t)n0 * H_;

    // per-thread copy coords: 256 16B-units per array, 2 per thread
    const int row_c0 = tid >> 2,          u_c0 = (tid & 3);
    const int row_c1 = (tid + 128) >> 2,  u_c1 = ((tid + 128) & 3);

    // issue cp.async for one chunk into a stage
    auto issue = [&](int st, int k0) {
        CP16(s2u(&sA_hi[st][row_c0][u_c0 * 8]),
             Ahi + (size_t)row_c0 * H_ + k0 + u_c0 * 8);
        CP16(s2u(&sA_hi[st][row_c1][u_c1 * 8]),
             Ahi + (size_t)row_c1 * H_ + k0 + u_c1 * 8);
        CP16(s2u(&sA_lo[st][row_c0][u_c0 * 8]),
             Alo + (size_t)row_c0 * H_ + k0 + u_c0 * 8);
        CP16(s2u(&sA_lo[st][row_c1][u_c1 * 8]),
             Alo + (size_t)row_c1 * H_ + k0 + u_c1 * 8);
        CP16(s2u(&sB_hi[st][row_c0][u_c0 * 8]),
             Bhi + (size_t)row_c0 * H_ + k0 + u_c0 * 8);
        CP16(s2u(&sB_hi[st][row_c1][u_c1 * 8]),
             Bhi + (size_t)row_c1 * H_ + k0 + u_c1 * 8);
        CP16(s2u(&sB_lo[st][row_c0][u_c0 * 8]),
             Blo + (size_t)row_c0 * H_ + k0 + u_c0 * 8);
        CP16(s2u(&sB_lo[st][row_c1][u_c1 * 8]),
             Blo + (size_t)row_c1 * H_ + k0 + u_c1 * 8);
    };

    issue(0, 0);
    asm volatile("cp.async.commit_group;" ::: "memory");

    float acc[2][4][4] = {};

    for (int ck = 0; ck < NCHUNK; ++ck) {
        asm volatile("cp.async.wait_group 0;" ::: "memory");
        __syncthreads();   // stage ck ready; prev compute done everywhere
        if (ck + 1 < NCHUNK) issue((ck + 1) & 1, (ck + 1) * KC);
        asm volatile("cp.async.commit_group;" ::: "memory");

        const int st = ck & 1;
        #pragma unroll
        for (int ks = 0; ks < 2; ++ks) {
            const int kw = ks * 16;
            uint32_t ah[2][4], al[2][4], bh[2][4], bl[2][4];
            #pragma unroll
            for (int mt = 0; mt < 2; ++mt) {
                int row = warp_m * 32 + mt * 16 + (lane & 15);
                int col = kw + ((lane >> 4) << 3);
                ldsm_x4(ah[mt], s2u(&sA_hi[st][row][col]));
                ldsm_x4(al[mt], s2u(&sA_lo[st][row][col]));
            }
            #pragma unroll
            for (int np = 0; np < 2; ++np) {
                int row = warp_n * 32 + np * 16 + (lane & 7) +
                          ((lane >> 4) << 3);
                int col = kw + (((lane >> 3) & 1) << 3);
                ldsm_x4(bh[np], s2u(&sB_hi[st][row][col]));
                ldsm_x4(bl[np], s2u(&sB_lo[st][row][col]));
            }
            #pragma unroll
            for (int mt = 0; mt < 2; ++mt) {
                #pragma unroll
                for (int nt = 0; nt < 4; ++nt) {
                    const uint32_t* bhp = &bh[nt >> 1][(nt & 1) * 2];
                    const uint32_t* blp = &bl[nt >> 1][(nt & 1) * 2];
                    mma_bf16(acc[mt][nt], ah[mt], bhp);
                    mma_bf16(acc[mt][nt], ah[mt], blp);
                    mma_bf16(acc[mt][nt], al[mt], bhp);
                }
            }
        }
    }

    // ---- epilogue: bias + SELU + partial logits ----
    const float kScale = 1.0507009873554805f;
    const float kAlpha = 1.6732632423543772f;
    float pl[4][C_] = {};   // ridx = mt*2 + upper8
    #pragma unroll
    for (int mt = 0; mt < 2; ++mt) {
        #pragma unroll
        for (int nt = 0; nt < 4; ++nt) {
            #pragma unroll
            for (int e = 0; e < 4; ++e) {
                int col = warp_n * 32 + nt * 8 + (lane & 3) * 2 + (e & 1);
                float x = acc[mt][nt][e] + sBias[col];
                float y = (x > 0.0f) ? x : kAlpha * expm1f(x);
                float h = kScale * y;
                int ridx = mt * 2 + (e >> 1);
                #pragma unroll
                for (int c = 0; c < C_; ++c)
                    pl[ridx][c] = fmaf(h, sWo[col * C_ + c], pl[ridx][c]);
            }
        }
    }
    #pragma unroll
    for (int ridx = 0; ridx < 4; ++ridx)
        #pragma unroll
        for (int c = 0; c < C_; ++c) {
            pl[ridx][c] += __shfl_xor_sync(0xFFFFFFFFu, pl[ridx][c], 1);
            pl[ridx][c] += __shfl_xor_sync(0xFFFFFFFFu, pl[ridx][c], 2);
        }
    if ((lane & 3) == 0) {
        const int slot = blockIdx.x * 2 + warp_n;
        #pragma unroll
        for (int ridx = 0; ridx < 4; ++ridx) {
            int row = m0 + warp_m * 32 + (ridx >> 1) * 16 + (lane >> 2) +
                      (ridx & 1) * 8;
            float* dst = g_partial + ((size_t)slot * NSEG + row) * C_;
            #pragma unroll
            for (int c = 0; c < C_; ++c) dst[c] = pl[ridx][c];
        }
    }
}

// ---------------------------------------------------------------------------
// Kernel 3: reduce 24 partial slots + b_o, softmax.  grid=4, block=256.
// ---------------------------------------------------------------------------
__global__ __launch_bounds__(256) void softmax_kernel(
    const float* __restrict__ bo, float* __restrict__ out) {
    int row = blockIdx.x * 256 + threadIdx.x;
    float l[C_];
    #pragma unroll
    for (int c = 0; c < C_; ++c) l[c] = bo[c];
    #pragma unroll
    for (int t = 0; t < NTILE_P; ++t) {
        const float* p = g_partial + ((size_t)t * NSEG + row) * C_;
        #pragma unroll
        for (int c = 0; c < C_; ++c) l[c] += p[c];
    }
    float mx = -INFINITY;
    #pragma unroll
    for (int c = 0; c < C_; ++c) mx = fmaxf(mx, l[c]);
    float sum = 0.0f;
    #pragma unroll
    for (int c = 0; c < C_; ++c) { l[c] = expf(l[c] - mx); sum += l[c]; }
    float inv = 1.0f / sum;
    #pragma unroll
    for (int c = 0; c < C_; ++c) out[(size_t)row * C_ + c] = l[c] * inv;
}

// ---------------------------------------------------------------------------
// Launch
// ---------------------------------------------------------------------------
extern "C" void kernel_launch(void* const* d_in, const int* in_sizes, int n_in,
                              void* d_out, int out_size) {
    const float* hidden = (const float*)d_in[0];
    const int*   seg    = (const int*)d_in[1];
    int base = (n_in >= 7) ? 3 : 2;
    const float* W_h = (const float*)d_in[base + 0];
    const float* b_h = (const float*)d_in[base + 1];
    const float* W_o = (const float*)d_in[base + 2];
    const float* b_o = (const float*)d_in[base + 3];
    float* out = (float*)d_out;

    prep_kernel<<<NSEG + NWPREP, 256>>>(hidden, seg, W_h);

    dim3 gg(NTILE_N, NTILE_M);   // (12, 16) = 192 CTAs
    gemm_fused_kernel<<<gg, 128>>>(b_h, W_o);

    softmax_kernel<<<NSEG / 256, 256>>>(b_o, out);
}